// round 4
// baseline (speedup 1.0000x reference)
#include <cuda_runtime.h>
#include <cuda_pipeline.h>
#include <math_constants.h>

// FCOS decode — persistent blocks, 3-stage cp.async ring buffer.
//   inputs  : bbox [16,128,128,4] f32, center [16,128,128,1] f32, cls [16,128,128,80] f32
//   outputs : xywh [16,16384,4] f32 ++ cls_idx [16,16384] (as f32) ++ conf [16,16384] f32

#define N_LOC      (16 * 128 * 128)   // 262144
#define N_CLS      80
#define XYWH_ELEMS (N_LOC * 4)

#define THREADS        128
#define TILE           32                        // locations per pipeline stage
#define STAGES         3
#define F4_PER_ROW     (N_CLS / 4)               // 20
#define F4_PER_TILE    (TILE * F4_PER_ROW)       // 640  (10 KB)
#define F4_PER_THREAD  (F4_PER_TILE / THREADS)   // 5
#define N_TILES        (N_LOC / TILE)            // 8192

#define NUM_SMS        148
#define BLOCKS_PER_SM  7
#define GRID           (NUM_SMS * BLOCKS_PER_SM) // 1036

__global__ __launch_bounds__(THREADS)
void fcos_decode_kernel(const float4* __restrict__ cls4,
                        const float4* __restrict__ bbox4,
                        const float*  __restrict__ center,
                        float* __restrict__ out)
{
    __shared__ float4 sm[STAGES][F4_PER_TILE];   // 30 KB

    const int t      = threadIdx.x;
    const int stride = gridDim.x;
    const int row    = t >> 2;   // 0..31 (location within tile)
    const int part   = t & 3;    // 0..3  (20-class segment)

    // ---- prologue: issue loads for the first STAGES-1 tiles ----
    int issue_tile = blockIdx.x;
    #pragma unroll
    for (int s = 0; s < STAGES - 1; ++s) {
        if (issue_tile < N_TILES) {
            const float4* src = cls4 + (size_t)issue_tile * F4_PER_TILE;
            #pragma unroll
            for (int i = 0; i < F4_PER_THREAD; ++i)
                __pipeline_memcpy_async(&sm[s][t + i * THREADS],
                                        &src[t + i * THREADS], 16);
        }
        __pipeline_commit();
        issue_tile += stride;
    }

    int buf = 0;
    for (int k = blockIdx.x; k < N_TILES; k += stride) {
        // ---- issue load for tile k + (STAGES-1)*stride into ring slot ----
        {
            int sbuf = buf + (STAGES - 1);
            if (sbuf >= STAGES) sbuf -= STAGES;
            if (issue_tile < N_TILES) {
                const float4* src = cls4 + (size_t)issue_tile * F4_PER_TILE;
                #pragma unroll
                for (int i = 0; i < F4_PER_THREAD; ++i)
                    __pipeline_memcpy_async(&sm[sbuf][t + i * THREADS],
                                            &src[t + i * THREADS], 16);
            }
            __pipeline_commit();
            issue_tile += stride;
        }
        __pipeline_wait_prior(STAGES - 1);   // tile k's group complete
        __syncthreads();                     // cross-thread smem visibility

        // ---- per-thread partial max/argmax over 20 classes (sigmoid monotonic) ----
        const float4* my = &sm[buf][row * F4_PER_ROW + part * 5];
        float best = -CUDART_INF_F;
        int   bidx = 0;
        #pragma unroll
        for (int j = 0; j < 5; ++j) {
            float4 v = my[j];
            int b0 = part * 20 + j * 4;
            if (v.x > best) { best = v.x; bidx = b0 + 0; }
            if (v.y > best) { best = v.y; bidx = b0 + 1; }
            if (v.z > best) { best = v.z; bidx = b0 + 2; }
            if (v.w > best) { best = v.w; bidx = b0 + 3; }
        }

        // ---- combine the 4 segment-partials (tie -> lowest class index) ----
        #pragma unroll
        for (int off = 1; off <= 2; off <<= 1) {
            float ob = __shfl_xor_sync(0xffffffffu, best, off);
            int   oi = __shfl_xor_sync(0xffffffffu, bidx, off);
            if (ob > best || (ob == best && oi < bidx)) { best = ob; bidx = oi; }
        }

        // ---- owner lane: bbox decode + confidence + writes ----
        if (part == 0) {
            int loc = k * TILE + row;

            float4 bb = bbox4[loc];
            float l  = __expf(bb.x) * 8.0f;
            float tt = __expf(bb.y) * 8.0f;
            float r  = __expf(bb.z) * 8.0f;
            float bo = __expf(bb.w) * 8.0f;

            int h = (loc >> 7) & 127;
            int w =  loc       & 127;

            float4 xywh;
            xywh.x = ((float)w * 8.0f + 4.0f) - (l  - r ) * 0.5f;
            xywh.y = ((float)h * 8.0f + 4.0f) - (tt - bo) * 0.5f;
            xywh.z = l  + r;
            xywh.w = tt + bo;

            float s_ctr = 1.0f / (1.0f + __expf(-center[loc]));
            float s_cls = 1.0f / (1.0f + __expf(-best));

            reinterpret_cast<float4*>(out)[loc] = xywh;
            out[XYWH_ELEMS + loc]               = (float)bidx;
            out[XYWH_ELEMS + N_LOC + loc]       = sqrtf(s_ctr * s_cls);
        }

        __syncthreads();   // all reads of sm[buf] done before next iter reuses it
        ++buf;
        if (buf == STAGES) buf = 0;
    }
}

extern "C" void kernel_launch(void* const* d_in, const int* in_sizes, int n_in,
                              void* d_out, int out_size)
{
    const float* bbox   = (const float*)d_in[0];
    const float* center = (const float*)d_in[1];
    const float* cls    = (const float*)d_in[2];
    float* out = (float*)d_out;

    fcos_decode_kernel<<<GRID, THREADS>>>(
        reinterpret_cast<const float4*>(cls),
        reinterpret_cast<const float4*>(bbox),
        center, out);
}